// round 14
// baseline (speedup 1.0000x reference)
#include <cuda_runtime.h>

// CorrelationMSELoss — B=8192 rows, L=1024 labels, single fused kernel.
// out = mean((pred-label)^2) + sum_rows(row_loss)
// Grid 128 x 1024 threads: each warp owns TWO rows (interleaved loads for
// natural MLP). CTA-count-scaling overhead term minimized further.

static constexpr int B_ROWS = 8192;
static constexpr int L_COLS = 1024;
static constexpr int WARPS_PER_BLOCK = 32;
static constexpr int THREADS = WARPS_PER_BLOCK * 32;        // 1024
static constexpr int ROWS_PER_WARP = 2;
static constexpr int ROWS_PER_BLOCK = WARPS_PER_BLOCK * ROWS_PER_WARP;  // 64
static constexpr int GRID = B_ROWS / ROWS_PER_BLOCK;        // 128 blocks

__device__ double g_sum_mse = 0.0;
__device__ double g_sum_loss = 0.0;
__device__ unsigned int g_count = 0;  // reset by last block each launch

__device__ __forceinline__ float ex2_approx(float x) {
    float r;
    asm("ex2.approx.ftz.f32 %0, %1;" : "=f"(r) : "f"(x));
    return r;
}

// fire-and-forget f64 reduction (REDG: no return trip on the critical path)
__device__ __forceinline__ void red_add_f64(double* addr, double v) {
    asm volatile("red.global.add.f64 [%0], %1;" :: "l"(addr), "d"(v) : "memory");
}

__device__ __forceinline__ void accum_chunk(float4 p, float4 l, float& mse,
                                            float& spos, float& stot, float& none) {
    constexpr float L2E = 1.4426950408889634f;  // log2(e)
    float pe[4] = {p.x, p.y, p.z, p.w};
    float le[4] = {l.x, l.y, l.z, l.w};
#pragma unroll
    for (int j = 0; j < 4; ++j) {
        float pv = pe[j], lv = le[j];
        float d = pv - lv;
        mse = fmaf(d, d, mse);
        float t = pv * L2E;
        float arg = fmaf(lv, -2.f * t, t);  // +t for lv=0, -t for lv=1
        float e = ex2_approx(arg);
        stot += e;
        spos = fmaf(lv, e, spos);
        none += lv;  // exact integer count
    }
}

// row loss from reduced (already warp-summed) quantities
__device__ __forceinline__ float row_loss(float spos, float stot, float none) {
    float n1 = none;
    float n0 = (float)L_COLS - none;
    float sneg = stot - spos;
    if (n1 == 0.f) return sneg * 0.36787944117144233f / fmaxf(n0, 1.f);
    if (n0 == 0.f) return spos / n1;
    return (spos * sneg) / (n1 * n0);
}

__global__ __launch_bounds__(THREADS) void k_fused(const float* __restrict__ pred,
                                                   const float* __restrict__ label,
                                                   float* __restrict__ out) {
    const int lane = threadIdx.x & 31;
    const int warp = threadIdx.x >> 5;
    const int row0 = blockIdx.x * ROWS_PER_BLOCK + warp * ROWS_PER_WARP;  // and row0+1

    const float4* p4 = reinterpret_cast<const float4*>(pred) + (long)row0 * (L_COLS / 4) + lane;
    const float4* l4 = reinterpret_cast<const float4*>(label) + (long)row0 * (L_COLS / 4) + lane;
    constexpr int RSTRIDE = L_COLS / 4;  // float4s per row

    float mse = 0.f;
    float spos0 = 0.f, stot0 = 0.f, none0 = 0.f;
    float spos1 = 0.f, stot1 = 0.f, none1 = 0.f;

#pragma unroll
    for (int i = 0; i < L_COLS / 4 / 32; ++i) {  // 8 iterations, 2 rows interleaved
        float4 pa = __ldg(p4 + i * 32);
        float4 la = __ldg(l4 + i * 32);
        float4 pb = __ldg(p4 + RSTRIDE + i * 32);
        float4 lb = __ldg(l4 + RSTRIDE + i * 32);
        accum_chunk(pa, la, mse, spos0, stot0, none0);
        accum_chunk(pb, lb, mse, spos1, stot1, none1);
    }

    // warp reduction over both rows' accumulators
#pragma unroll
    for (int off = 16; off; off >>= 1) {
        mse   += __shfl_xor_sync(0xffffffffu, mse, off);
        spos0 += __shfl_xor_sync(0xffffffffu, spos0, off);
        stot0 += __shfl_xor_sync(0xffffffffu, stot0, off);
        none0 += __shfl_xor_sync(0xffffffffu, none0, off);
        spos1 += __shfl_xor_sync(0xffffffffu, spos1, off);
        stot1 += __shfl_xor_sync(0xffffffffu, stot1, off);
        none1 += __shfl_xor_sync(0xffffffffu, none1, off);
    }

    __shared__ float s_mse[WARPS_PER_BLOCK];
    __shared__ float s_loss[WARPS_PER_BLOCK];

    if (lane == 0) {
        s_mse[warp] = mse;
        s_loss[warp] = row_loss(spos0, stot0, none0) + row_loss(spos1, stot1, none1);
    }
    __syncthreads();

    // warp 0 folds the 32 per-warp results; lane 0 accumulates globally
    if (warp == 0) {
        float bm = s_mse[lane];
        float bl = s_loss[lane];
#pragma unroll
        for (int off = 16; off; off >>= 1) {
            bm += __shfl_xor_sync(0xffffffffu, bm, off);
            bl += __shfl_xor_sync(0xffffffffu, bl, off);
        }
        if (lane == 0) {
            red_add_f64(&g_sum_mse, (double)bm);
            red_add_f64(&g_sum_loss, (double)bl);
            __threadfence();
            unsigned int prev = atomicAdd(&g_count, 1u);
            if (prev == (unsigned)GRID - 1u) {
                __threadfence();
                double tm = g_sum_mse;
                double tl = g_sum_loss;
                out[0] = (float)(tm * (1.0 / ((double)B_ROWS * (double)L_COLS)) + tl);
                // reset for next graph replay (stream-ordered behind retirement)
                g_sum_mse = 0.0;
                g_sum_loss = 0.0;
                g_count = 0;
            }
        }
    }
}

extern "C" void kernel_launch(void* const* d_in, const int* in_sizes, int n_in,
                              void* d_out, int out_size) {
    const float* pred  = (const float*)d_in[0];
    const float* label = (const float*)d_in[1];
    float* out = (float*)d_out;
    k_fused<<<GRID, THREADS>>>(pred, label, out);
}

// round 15
// speedup vs baseline: 1.1178x; 1.1178x over previous
#include <cuda_runtime.h>

// CorrelationMSELoss — B=8192 rows, L=1024 labels, single fused kernel.
// out = mean((pred-label)^2) + sum_rows(row_loss)
// Balanced single wave: 296 CTAs (=148 SMs x 2) x 1024 threads; warp-per-row
// by global warp id, surplus warps contribute zero. REDG f64 epilogue.

static constexpr int B_ROWS = 8192;
static constexpr int L_COLS = 1024;
static constexpr int WARPS_PER_BLOCK = 32;
static constexpr int THREADS = WARPS_PER_BLOCK * 32;  // 1024
static constexpr int GRID = 296;                      // 148 SMs x 2 CTAs, one wave

__device__ double g_sum_mse = 0.0;
__device__ double g_sum_loss = 0.0;
__device__ unsigned int g_count = 0;  // reset by last block each launch

__device__ __forceinline__ float ex2_approx(float x) {
    float r;
    asm("ex2.approx.ftz.f32 %0, %1;" : "=f"(r) : "f"(x));
    return r;
}

// fire-and-forget f64 reduction (REDG: no return trip on the critical path)
__device__ __forceinline__ void red_add_f64(double* addr, double v) {
    asm volatile("red.global.add.f64 [%0], %1;" :: "l"(addr), "d"(v) : "memory");
}

__device__ __forceinline__ void accum_chunk(float4 p, float4 l, float& mse,
                                            float& spos, float& stot, float& none) {
    constexpr float L2E = 1.4426950408889634f;  // log2(e)
    float pe[4] = {p.x, p.y, p.z, p.w};
    float le[4] = {l.x, l.y, l.z, l.w};
#pragma unroll
    for (int j = 0; j < 4; ++j) {
        float pv = pe[j], lv = le[j];
        float d = pv - lv;
        mse = fmaf(d, d, mse);
        float t = pv * L2E;
        float arg = fmaf(lv, -2.f * t, t);  // +t for lv=0, -t for lv=1
        float e = ex2_approx(arg);
        stot += e;
        spos = fmaf(lv, e, spos);
        none += lv;  // exact integer count
    }
}

__global__ __launch_bounds__(THREADS) void k_fused(const float* __restrict__ pred,
                                                   const float* __restrict__ label,
                                                   float* __restrict__ out) {
    const int lane = threadIdx.x & 31;
    const int warp = threadIdx.x >> 5;
    const int gwarp = blockIdx.x * WARPS_PER_BLOCK + warp;  // global warp id
    const bool active = gwarp < B_ROWS;
    const int row = active ? gwarp : 0;  // inactive warps read row 0 (harmless) or skip

    const float4* p4 = reinterpret_cast<const float4*>(pred) + (long)row * (L_COLS / 4) + lane;
    const float4* l4 = reinterpret_cast<const float4*>(label) + (long)row * (L_COLS / 4) + lane;

    float mse = 0.f, spos = 0.f, stot = 0.f, none = 0.f;

    if (active) {
#pragma unroll
        for (int i = 0; i < L_COLS / 4 / 32; ++i) {  // 8 iterations
            float4 p = __ldg(p4 + i * 32);
            float4 l = __ldg(l4 + i * 32);
            accum_chunk(p, l, mse, spos, stot, none);
        }
    }

    // warp reduction (warp owns one row; inactive warps hold zeros)
#pragma unroll
    for (int off = 16; off; off >>= 1) {
        mse  += __shfl_xor_sync(0xffffffffu, mse, off);
        spos += __shfl_xor_sync(0xffffffffu, spos, off);
        stot += __shfl_xor_sync(0xffffffffu, stot, off);
        none += __shfl_xor_sync(0xffffffffu, none, off);
    }

    __shared__ float s_mse[WARPS_PER_BLOCK];
    __shared__ float s_loss[WARPS_PER_BLOCK];

    if (lane == 0) {
        float loss = 0.f;
        if (active) {
            float n1 = none;
            float n0 = (float)L_COLS - none;
            float sneg = stot - spos;
            if (n1 == 0.f) {
                loss = sneg * 0.36787944117144233f / fmaxf(n0, 1.f);  // e^{-1}*s_neg/n0
            } else if (n0 == 0.f) {
                loss = spos / n1;
            } else {
                loss = (spos * sneg) / (n1 * n0);
            }
        }
        s_mse[warp] = active ? mse : 0.f;
        s_loss[warp] = loss;
    }
    __syncthreads();

    // warp 0 folds the 32 per-warp results; lane 0 accumulates globally
    if (warp == 0) {
        float bm = s_mse[lane];
        float bl = s_loss[lane];
#pragma unroll
        for (int off = 16; off; off >>= 1) {
            bm += __shfl_xor_sync(0xffffffffu, bm, off);
            bl += __shfl_xor_sync(0xffffffffu, bl, off);
        }
        if (lane == 0) {
            // fire-and-forget sums; fence orders them before the counter bump
            red_add_f64(&g_sum_mse, (double)bm);
            red_add_f64(&g_sum_loss, (double)bl);
            __threadfence();
            unsigned int prev = atomicAdd(&g_count, 1u);
            if (prev == (unsigned)GRID - 1u) {
                // all other blocks' REDGs are globally visible (their fence
                // preceded their counter increment, which we observed)
                __threadfence();
                double tm = g_sum_mse;
                double tl = g_sum_loss;
                out[0] = (float)(tm * (1.0 / ((double)B_ROWS * (double)L_COLS)) + tl);
                // reset for next graph replay (stream-ordered behind retirement)
                g_sum_mse = 0.0;
                g_sum_loss = 0.0;
                g_count = 0;
            }
        }
    }
}

extern "C" void kernel_launch(void* const* d_in, const int* in_sizes, int n_in,
                              void* d_out, int out_size) {
    const float* pred  = (const float*)d_in[0];
    const float* label = (const float*)d_in[1];
    float* out = (float*)d_out;
    k_fused<<<GRID, THREADS>>>(pred, label, out);
}

// round 16
// speedup vs baseline: 1.2179x; 1.0896x over previous
#include <cuda_runtime.h>

// CorrelationMSELoss — B=8192 rows, L=1024 labels, single fused kernel.
// out = mean((pred-label)^2) + sum_rows(row_loss)
// Best-known config (re-verification): 256 CTAs x 1024 threads, warp-per-row,
// fire-and-forget REDG f64 accumulators + last-block finalize.

static constexpr int B_ROWS = 8192;
static constexpr int L_COLS = 1024;
static constexpr int WARPS_PER_BLOCK = 32;
static constexpr int THREADS = WARPS_PER_BLOCK * 32;   // 1024
static constexpr int GRID = B_ROWS / WARPS_PER_BLOCK;  // 256 blocks, one wave

__device__ double g_sum_mse = 0.0;
__device__ double g_sum_loss = 0.0;
__device__ unsigned int g_count = 0;  // reset by last block each launch

__device__ __forceinline__ float ex2_approx(float x) {
    float r;
    asm("ex2.approx.ftz.f32 %0, %1;" : "=f"(r) : "f"(x));
    return r;
}

// fire-and-forget f64 reduction (REDG: no return trip on the critical path)
__device__ __forceinline__ void red_add_f64(double* addr, double v) {
    asm volatile("red.global.add.f64 [%0], %1;" :: "l"(addr), "d"(v) : "memory");
}

__device__ __forceinline__ void accum_chunk(float4 p, float4 l, float& mse,
                                            float& spos, float& stot, float& none) {
    constexpr float L2E = 1.4426950408889634f;  // log2(e)
    float pe[4] = {p.x, p.y, p.z, p.w};
    float le[4] = {l.x, l.y, l.z, l.w};
#pragma unroll
    for (int j = 0; j < 4; ++j) {
        float pv = pe[j], lv = le[j];
        float d = pv - lv;
        mse = fmaf(d, d, mse);
        float t = pv * L2E;
        float arg = fmaf(lv, -2.f * t, t);  // +t for lv=0, -t for lv=1
        float e = ex2_approx(arg);
        stot += e;
        spos = fmaf(lv, e, spos);
        none += lv;  // exact integer count
    }
}

__global__ __launch_bounds__(THREADS) void k_fused(const float* __restrict__ pred,
                                                   const float* __restrict__ label,
                                                   float* __restrict__ out) {
    const int lane = threadIdx.x & 31;
    const int warp = threadIdx.x >> 5;
    const int row = blockIdx.x * WARPS_PER_BLOCK + warp;

    const float4* p4 = reinterpret_cast<const float4*>(pred) + (long)row * (L_COLS / 4) + lane;
    const float4* l4 = reinterpret_cast<const float4*>(label) + (long)row * (L_COLS / 4) + lane;

    float mse = 0.f, spos = 0.f, stot = 0.f, none = 0.f;

#pragma unroll
    for (int i = 0; i < L_COLS / 4 / 32; ++i) {  // 8 iterations
        float4 p = __ldg(p4 + i * 32);
        float4 l = __ldg(l4 + i * 32);
        accum_chunk(p, l, mse, spos, stot, none);
    }

    // warp reduction (warp owns one row)
#pragma unroll
    for (int off = 16; off; off >>= 1) {
        mse  += __shfl_xor_sync(0xffffffffu, mse, off);
        spos += __shfl_xor_sync(0xffffffffu, spos, off);
        stot += __shfl_xor_sync(0xffffffffu, stot, off);
        none += __shfl_xor_sync(0xffffffffu, none, off);
    }

    __shared__ float s_mse[WARPS_PER_BLOCK];
    __shared__ float s_loss[WARPS_PER_BLOCK];

    if (lane == 0) {
        float n1 = none;
        float n0 = (float)L_COLS - none;
        float sneg = stot - spos;
        float loss;
        if (n1 == 0.f) {
            loss = sneg * 0.36787944117144233f / fmaxf(n0, 1.f);  // e^{-1}*s_neg/n0
        } else if (n0 == 0.f) {
            loss = spos / n1;
        } else {
            loss = (spos * sneg) / (n1 * n0);
        }
        s_mse[warp] = mse;
        s_loss[warp] = loss;
    }
    __syncthreads();

    // warp 0 folds the 32 per-warp results; lane 0 accumulates globally
    if (warp == 0) {
        float bm = s_mse[lane];
        float bl = s_loss[lane];
#pragma unroll
        for (int off = 16; off; off >>= 1) {
            bm += __shfl_xor_sync(0xffffffffu, bm, off);
            bl += __shfl_xor_sync(0xffffffffu, bl, off);
        }
        if (lane == 0) {
            // fire-and-forget sums; fence orders them before the counter bump
            red_add_f64(&g_sum_mse, (double)bm);
            red_add_f64(&g_sum_loss, (double)bl);
            __threadfence();
            unsigned int prev = atomicAdd(&g_count, 1u);
            if (prev == (unsigned)GRID - 1u) {
                // all other blocks' REDGs are globally visible (their fence
                // preceded their counter increment, which we observed)
                __threadfence();
                double tm = g_sum_mse;
                double tl = g_sum_loss;
                out[0] = (float)(tm * (1.0 / ((double)B_ROWS * (double)L_COLS)) + tl);
                // reset for next graph replay (next launch is stream-ordered
                // behind full retirement of this one)
                g_sum_mse = 0.0;
                g_sum_loss = 0.0;
                g_count = 0;
            }
        }
    }
}

extern "C" void kernel_launch(void* const* d_in, const int* in_sizes, int n_in,
                              void* d_out, int out_size) {
    const float* pred  = (const float*)d_in[0];
    const float* label = (const float*)d_in[1];
    float* out = (float*)d_out;
    k_fused<<<GRID, THREADS>>>(pred, label, out);
}